// round 2
// baseline (speedup 1.0000x reference)
#include <cuda_runtime.h>
#include <math.h>

#define NB 2
#define NV 120000
#define NT 600000

#define TOTAL_E (NB * NT * 6)       // 7,200,000
#define TOTAL_T (NB * NT)           // 1,200,000
#define TOTAL_V (NB * NV)           //   240,000
#define PTS_FLOATS ((size_t)TOTAL_E * 3)  // 21,600,000

// ---------------- scratch (device globals; no allocations allowed) ----------
__device__ double g_meansum[8];   // [b][c] channel sums
__device__ float  g_mean[8];      // finalized means
__device__ double g_acc[3];       // L1 sumsq, L2 sum, L3 sum
__device__ float  g_term[TOTAL_V * 4];
__device__ float  g_cnt[TOTAL_V];

// ---------------- K0: zero scratch (graph-safe, no host API) -----------------
__global__ void k_zero()
{
    int gid = blockIdx.x * 256 + threadIdx.x;
    if (gid < TOTAL_V) {
        reinterpret_cast<float4*>(g_term)[gid] = make_float4(0.f, 0.f, 0.f, 0.f);
        g_cnt[gid] = 0.f;
    }
    if (gid < 8) g_meansum[gid] = 0.0;
    if (gid < 3) g_acc[gid] = 0.0;
}

// ---------------- K1: per-batch per-channel sums of pred ---------------------
__global__ void k_mean(const float4* __restrict__ pred)
{
    int b = blockIdx.y;
    int i = blockIdx.x * 256 + threadIdx.x;
    float4 v = make_float4(0.f, 0.f, 0.f, 0.f);
    if (i < NV) v = pred[b * NV + i];
    #pragma unroll
    for (int o = 16; o; o >>= 1) {
        v.x += __shfl_down_sync(0xFFFFFFFFu, v.x, o);
        v.y += __shfl_down_sync(0xFFFFFFFFu, v.y, o);
        v.z += __shfl_down_sync(0xFFFFFFFFu, v.z, o);
        v.w += __shfl_down_sync(0xFFFFFFFFu, v.w, o);
    }
    if ((threadIdx.x & 31) == 0) {
        atomicAdd(&g_meansum[b * 4 + 0], (double)v.x);
        atomicAdd(&g_meansum[b * 4 + 1], (double)v.y);
        atomicAdd(&g_meansum[b * 4 + 2], (double)v.z);
        atomicAdd(&g_meansum[b * 4 + 3], (double)v.w);
    }
}

__global__ void k_prep()
{
    int t = threadIdx.x;
    if (t < 8) g_mean[t] = (float)(g_meansum[t] / (double)NV);
}

// ---------------- K2: fused per-tet kernel -----------------------------------
// For each tet: load 4 verts once; do Laplacian scatter (mean-invariant, raw
// pred); compute all 6 edges (L2/L3 terms, intersection pts, mask); stage
// pts/mask in smem for coalesced stores.
__global__ void __launch_bounds__(256) k_tet(
    const float4* __restrict__ pred, const int4* __restrict__ tetra,
    float* __restrict__ out)
{
    __shared__ float s_pts[256 * 18];   // 18 KB
    __shared__ float s_msk[256 * 6];    //  6 KB
    __shared__ float s2[8], s3[8];

    int tid = threadIdx.x;
    int gid = blockIdx.x * 256 + tid;
    bool valid = gid < TOTAL_T;

    float l2sum = 0.f, l3sum = 0.f;

    if (valid) {
        int b = (gid >= NT) ? 1 : 0;
        int4 f = tetra[gid];
        const float4* p = pred + (size_t)b * NV;
        float4 v[4];
        v[0] = p[f.x]; v[1] = p[f.y]; v[2] = p[f.z]; v[3] = p[f.w];

        float sx = v[0].x + v[1].x + v[2].x + v[3].x;
        float sy = v[0].y + v[1].y + v[2].y + v[3].y;
        float sz = v[0].z + v[1].z + v[2].z + v[3].z;
        float sw = v[0].w + v[1].w + v[2].w + v[3].w;

        // ---- Laplacian scatter (mean cancels in vsum - 4v) ----
        int base = b * NV;
        int vi[4] = {f.x, f.y, f.z, f.w};
        #pragma unroll
        for (int k = 0; k < 4; k++) {
            float* tb = &g_term[(size_t)(base + vi[k]) * 4];
            atomicAdd(tb + 0, sx - 4.f * v[k].x);
            atomicAdd(tb + 1, sy - 4.f * v[k].y);
            atomicAdd(tb + 2, sz - 4.f * v[k].z);
            atomicAdd(tb + 3, sw - 4.f * v[k].w);
            atomicAdd(&g_cnt[base + vi[k]], 1.f);
        }

        // ---- 6 edges ----
        float mx = g_mean[b * 4 + 0];
        float my = g_mean[b * 4 + 1];
        float mz = g_mean[b * 4 + 2];
        float mw = g_mean[b * 4 + 3];

        const int EA[6] = {0, 0, 0, 1, 1, 2};
        const int EB[6] = {1, 2, 3, 2, 3, 3};
        #pragma unroll
        for (int e = 0; e < 6; e++) {
            float4 va = v[EA[e]];
            float4 vb = v[EB[e]];
            float wa = va.w - mw;
            float wb = vb.w - mw;
            float prod = wa * wb;           // ALPHA = 0
            l2sum += prod;

            float dx = va.x - vb.x;         // mean cancels in diffs
            float dy = va.y - vb.y;
            float dz = va.z - vb.z;
            float dw = va.w - vb.w;
            float nrm = sqrtf(dx * dx + dy * dy + dz * dz + dw * dw);
            float l3 = nrm - 0.4f;
            l3sum += l3 * l3;

            float safe_q = (fabsf(dw) > 1e-12f) ? dw : 1.0f;
            float t = -wa / safe_q;

            bool m = prod < 0.f;
            float px = 0.f, py = 0.f, pz = 0.f;
            if (m) {
                px = (va.x - mx) + t * dx;
                py = (va.y - my) + t * dy;
                pz = (va.z - mz) + t * dz;
            }
            s_pts[tid * 18 + e * 3 + 0] = px;
            s_pts[tid * 18 + e * 3 + 1] = py;
            s_pts[tid * 18 + e * 3 + 2] = pz;
            s_msk[tid * 6 + e] = m ? 1.f : 0.f;
        }
    }

    // ---- block reduce L2 / L3 ----
    #pragma unroll
    for (int o = 16; o; o >>= 1) {
        l2sum += __shfl_down_sync(0xFFFFFFFFu, l2sum, o);
        l3sum += __shfl_down_sync(0xFFFFFFFFu, l3sum, o);
    }
    if ((tid & 31) == 0) { s2[tid >> 5] = l2sum; s3[tid >> 5] = l3sum; }
    __syncthreads();

    // ---- coalesced writeout ----
    int nvalid = TOTAL_T - blockIdx.x * 256;
    if (nvalid > 256) nvalid = 256;

    size_t pbase = 4 + (size_t)blockIdx.x * (256 * 18);
    int totp = nvalid * 18;
    for (int i = tid; i < totp; i += 256) out[pbase + i] = s_pts[i];

    size_t mbase = 4 + PTS_FLOATS + (size_t)blockIdx.x * (256 * 6);
    int totm = nvalid * 6;
    for (int i = tid; i < totm; i += 256) out[mbase + i] = s_msk[i];

    if (tid == 0) {
        float a2 = 0.f, a3 = 0.f;
        #pragma unroll
        for (int i = 0; i < 8; i++) { a2 += s2[i]; a3 += s3[i]; }
        atomicAdd(&g_acc[1], (double)a2);
        atomicAdd(&g_acc[2], (double)a3);
    }
}

// ---------------- K3: per-vertex L1 finalize ---------------------------------
__global__ void k_vert()
{
    int gid = blockIdx.x * 256 + threadIdx.x;
    float s = 0.f;
    if (gid < TOTAL_V) {
        float4 t = reinterpret_cast<const float4*>(g_term)[gid];
        float c = g_cnt[gid];
        float inv = 1.f / fmaxf(3.f * c, 1.f);
        float ax = t.x * inv, ay = t.y * inv, az = t.z * inv, aw = t.w * inv;
        s = ax * ax + ay * ay + az * az + aw * aw;
    }
    #pragma unroll
    for (int o = 16; o; o >>= 1) s += __shfl_down_sync(0xFFFFFFFFu, s, o);
    __shared__ float sh[8];
    if ((threadIdx.x & 31) == 0) sh[threadIdx.x >> 5] = s;
    __syncthreads();
    if (threadIdx.x == 0) {
        float a = 0.f;
        #pragma unroll
        for (int i = 0; i < 8; i++) a += sh[i];
        atomicAdd(&g_acc[0], (double)a);
    }
}

// ---------------- K4: write losses -------------------------------------------
__global__ void k_final(float* __restrict__ out)
{
    if (threadIdx.x == 0) {
        out[0] = (float)(g_acc[0] / (double)((size_t)NB * NV * 4));
        out[1] = (float)(g_acc[1] / (double)TOTAL_E);
        out[2] = (float)(g_acc[2] / (double)TOTAL_E);
        out[3] = 0.f;
    }
}

// ---------------- launch ------------------------------------------------------
extern "C" void kernel_launch(void* const* d_in, const int* in_sizes, int n_in,
                              void* d_out, int out_size)
{
    const float4* pred  = (const float4*)d_in[0];   // (B, N, 4) fp32
    const int4*   tetra = (const int4*)d_in[1];     // (B, T, 4) int32
    float* out = (float*)d_out;

    k_zero<<<(TOTAL_V + 255) / 256, 256>>>();
    dim3 gm((NV + 255) / 256, NB);
    k_mean<<<gm, 256>>>(pred);
    k_prep<<<1, 8>>>();
    k_tet<<<(TOTAL_T + 255) / 256, 256>>>(pred, tetra, out);
    k_vert<<<(TOTAL_V + 255) / 256, 256>>>();
    k_final<<<1, 32>>>(out);
}

// round 3
// speedup vs baseline: 2.9861x; 2.9861x over previous
#include <cuda_runtime.h>
#include <math.h>

#define NB 2
#define NV 120000
#define NT 600000

#define TOTAL_E (NB * NT * 6)       // 7,200,000
#define TOTAL_T (NB * NT)           // 1,200,000
#define TOTAL_V (NB * NV)           //   240,000
#define PTS_FLOATS ((size_t)TOTAL_E * 3)  // 21,600,000

// ---------------- scratch (device globals; no allocations allowed) ----------
__device__ double g_meansum[8];          // [b][c] channel sums
__device__ float  g_mean[8];             // finalized means
__device__ double g_acc[3];              // L1 sumsq, L2 sum, L3 sum
__device__ float4 g_term[TOTAL_V];       // 16B-aligned for red.v4
__device__ float  g_cnt[TOTAL_V];

__device__ __forceinline__ void red_add_v4(float4* addr, float a, float b, float c, float d)
{
    asm volatile("red.global.add.v4.f32 [%0], {%1, %2, %3, %4};"
                 :: "l"(addr), "f"(a), "f"(b), "f"(c), "f"(d) : "memory");
}

// ---------------- K0: zero scratch -------------------------------------------
__global__ void k_zero()
{
    int gid = blockIdx.x * 256 + threadIdx.x;
    if (gid < TOTAL_V) {
        g_term[gid] = make_float4(0.f, 0.f, 0.f, 0.f);
        g_cnt[gid] = 0.f;
    }
    if (gid < 8) g_meansum[gid] = 0.0;
    if (gid < 3) g_acc[gid] = 0.0;
}

// ---------------- K1: per-batch per-channel sums (low-contention) ------------
#define MEAN_BLKS 60
__global__ void k_mean(const float4* __restrict__ pred)
{
    int b = blockIdx.y;
    float sx = 0.f, sy = 0.f, sz = 0.f, sw = 0.f;
    for (int i = blockIdx.x * 256 + threadIdx.x; i < NV; i += MEAN_BLKS * 256) {
        float4 v = pred[b * NV + i];
        sx += v.x; sy += v.y; sz += v.z; sw += v.w;
    }
    #pragma unroll
    for (int o = 16; o; o >>= 1) {
        sx += __shfl_down_sync(0xFFFFFFFFu, sx, o);
        sy += __shfl_down_sync(0xFFFFFFFFu, sy, o);
        sz += __shfl_down_sync(0xFFFFFFFFu, sz, o);
        sw += __shfl_down_sync(0xFFFFFFFFu, sw, o);
    }
    __shared__ float sh[8][4];
    if ((threadIdx.x & 31) == 0) {
        int w = threadIdx.x >> 5;
        sh[w][0] = sx; sh[w][1] = sy; sh[w][2] = sz; sh[w][3] = sw;
    }
    __syncthreads();
    if (threadIdx.x == 0) {
        float ax = 0.f, ay = 0.f, az = 0.f, aw = 0.f;
        #pragma unroll
        for (int i = 0; i < 8; i++) { ax += sh[i][0]; ay += sh[i][1]; az += sh[i][2]; aw += sh[i][3]; }
        atomicAdd(&g_meansum[b * 4 + 0], (double)ax);
        atomicAdd(&g_meansum[b * 4 + 1], (double)ay);
        atomicAdd(&g_meansum[b * 4 + 2], (double)az);
        atomicAdd(&g_meansum[b * 4 + 3], (double)aw);
    }
}

__global__ void k_prep()
{
    int t = threadIdx.x;
    if (t < 8) g_mean[t] = (float)(g_meansum[t] / (double)NV);
}

// ---------------- K2: fused per-tet kernel -----------------------------------
__global__ void __launch_bounds__(256) k_tet(
    const float4* __restrict__ pred, const int4* __restrict__ tetra,
    float* __restrict__ out)
{
    __shared__ float s_pts[256 * 18];   // 18 KB
    __shared__ float s_msk[256 * 6];    //  6 KB
    __shared__ float s2[8], s3[8];

    int tid = threadIdx.x;
    int gid = blockIdx.x * 256 + tid;
    bool valid = gid < TOTAL_T;

    float l2sum = 0.f, l3sum = 0.f;

    if (valid) {
        int b = (gid >= NT) ? 1 : 0;
        int4 f = tetra[gid];
        const float4* p = pred + (size_t)b * NV;
        float4 v[4];
        v[0] = p[f.x]; v[1] = p[f.y]; v[2] = p[f.z]; v[3] = p[f.w];

        float sx = v[0].x + v[1].x + v[2].x + v[3].x;
        float sy = v[0].y + v[1].y + v[2].y + v[3].y;
        float sz = v[0].z + v[1].z + v[2].z + v[3].z;
        float sw = v[0].w + v[1].w + v[2].w + v[3].w;

        // ---- Laplacian scatter: 1 v4-RED + 1 scalar RED per vertex ----
        int base = b * NV;
        int vi[4] = {f.x, f.y, f.z, f.w};
        #pragma unroll
        for (int k = 0; k < 4; k++) {
            red_add_v4(&g_term[base + vi[k]],
                       sx - 4.f * v[k].x, sy - 4.f * v[k].y,
                       sz - 4.f * v[k].z, sw - 4.f * v[k].w);
            atomicAdd(&g_cnt[base + vi[k]], 1.f);
        }

        // ---- 6 edges ----
        float mx = g_mean[b * 4 + 0];
        float my = g_mean[b * 4 + 1];
        float mz = g_mean[b * 4 + 2];
        float mw = g_mean[b * 4 + 3];

        const int EA[6] = {0, 0, 0, 1, 1, 2};
        const int EB[6] = {1, 2, 3, 2, 3, 3};
        #pragma unroll
        for (int e = 0; e < 6; e++) {
            float4 va = v[EA[e]];
            float4 vb = v[EB[e]];
            float wa = va.w - mw;
            float wb = vb.w - mw;
            float prod = wa * wb;           // ALPHA = 0
            l2sum += prod;

            float dx = va.x - vb.x;
            float dy = va.y - vb.y;
            float dz = va.z - vb.z;
            float dw = va.w - vb.w;
            float nrm = sqrtf(dx * dx + dy * dy + dz * dz + dw * dw);
            float l3 = nrm - 0.4f;
            l3sum += l3 * l3;

            float safe_q = (fabsf(dw) > 1e-12f) ? dw : 1.0f;
            float t = -wa / safe_q;

            bool m = prod < 0.f;
            float px = 0.f, py = 0.f, pz = 0.f;
            if (m) {
                px = (va.x - mx) + t * dx;
                py = (va.y - my) + t * dy;
                pz = (va.z - mz) + t * dz;
            }
            s_pts[tid * 18 + e * 3 + 0] = px;
            s_pts[tid * 18 + e * 3 + 1] = py;
            s_pts[tid * 18 + e * 3 + 2] = pz;
            s_msk[tid * 6 + e] = m ? 1.f : 0.f;
        }
    }

    // ---- block reduce L2 / L3 ----
    #pragma unroll
    for (int o = 16; o; o >>= 1) {
        l2sum += __shfl_down_sync(0xFFFFFFFFu, l2sum, o);
        l3sum += __shfl_down_sync(0xFFFFFFFFu, l3sum, o);
    }
    if ((tid & 31) == 0) { s2[tid >> 5] = l2sum; s3[tid >> 5] = l3sum; }
    __syncthreads();

    // ---- coalesced vectorized writeout (all bases 16B aligned) ----
    int nvalid = TOTAL_T - blockIdx.x * 256;
    if (nvalid > 256) nvalid = 256;

    const float4* sp4 = reinterpret_cast<const float4*>(s_pts);
    const float4* sm4 = reinterpret_cast<const float4*>(s_msk);

    float4* op = reinterpret_cast<float4*>(out + 4 + (size_t)blockIdx.x * (256 * 18));
    int np4 = nvalid * 18 / 4;                 // 1152 or multiple of 4-safe (nvalid*18 div by 4)
    for (int i = tid; i < np4; i += 256) op[i] = sp4[i];

    float4* om = reinterpret_cast<float4*>(out + 4 + PTS_FLOATS + (size_t)blockIdx.x * (256 * 6));
    int nm4 = nvalid * 6 / 4;
    for (int i = tid; i < nm4; i += 256) om[i] = sm4[i];

    // tail floats if nvalid*18 or *6 not divisible by 4 (nvalid=128/256 -> divisible)
    if (tid == 0) {
        float a2 = 0.f, a3 = 0.f;
        #pragma unroll
        for (int i = 0; i < 8; i++) { a2 += s2[i]; a3 += s3[i]; }
        atomicAdd(&g_acc[1], (double)a2);
        atomicAdd(&g_acc[2], (double)a3);
    }
}

// ---------------- K3: per-vertex L1 finalize ---------------------------------
__global__ void k_vert()
{
    int gid = blockIdx.x * 256 + threadIdx.x;
    float s = 0.f;
    if (gid < TOTAL_V) {
        float4 t = g_term[gid];
        float c = g_cnt[gid];
        float inv = 1.f / fmaxf(3.f * c, 1.f);
        float ax = t.x * inv, ay = t.y * inv, az = t.z * inv, aw = t.w * inv;
        s = ax * ax + ay * ay + az * az + aw * aw;
    }
    #pragma unroll
    for (int o = 16; o; o >>= 1) s += __shfl_down_sync(0xFFFFFFFFu, s, o);
    __shared__ float sh[8];
    if ((threadIdx.x & 31) == 0) sh[threadIdx.x >> 5] = s;
    __syncthreads();
    if (threadIdx.x == 0) {
        float a = 0.f;
        #pragma unroll
        for (int i = 0; i < 8; i++) a += sh[i];
        atomicAdd(&g_acc[0], (double)a);
    }
}

// ---------------- K4: write losses -------------------------------------------
__global__ void k_final(float* __restrict__ out)
{
    if (threadIdx.x == 0) {
        out[0] = (float)(g_acc[0] / (double)((size_t)NB * NV * 4));
        out[1] = (float)(g_acc[1] / (double)TOTAL_E);
        out[2] = (float)(g_acc[2] / (double)TOTAL_E);
        out[3] = 0.f;
    }
}

// ---------------- launch ------------------------------------------------------
extern "C" void kernel_launch(void* const* d_in, const int* in_sizes, int n_in,
                              void* d_out, int out_size)
{
    const float4* pred  = (const float4*)d_in[0];   // (B, N, 4) fp32
    const int4*   tetra = (const int4*)d_in[1];     // (B, T, 4) int32
    float* out = (float*)d_out;

    k_zero<<<(TOTAL_V + 255) / 256, 256>>>();
    dim3 gm(MEAN_BLKS, NB);
    k_mean<<<gm, 256>>>(pred);
    k_prep<<<1, 8>>>();
    k_tet<<<(TOTAL_T + 255) / 256, 256>>>(pred, tetra, out);
    k_vert<<<(TOTAL_V + 255) / 256, 256>>>();
    k_final<<<1, 32>>>(out);
}

// round 4
// speedup vs baseline: 3.0162x; 1.0101x over previous
#include <cuda_runtime.h>
#include <math.h>

#define NB 2
#define NV 120000
#define NT 600000

#define TOTAL_E (NB * NT * 6)       // 7,200,000
#define TOTAL_T (NB * NT)           // 1,200,000
#define TOTAL_V (NB * NV)           //   240,000
#define PTS_FLOATS ((size_t)TOTAL_E * 3)  // 21,600,000

#define MEAN_SUB 60
#define ZERO_BLKS ((TOTAL_V * 2 + 255) / 256)          // 1875
#define INIT_BLKS (ZERO_BLKS + NB * MEAN_SUB)          // 1995
#define VERT_BLKS ((TOTAL_V + 255) / 256)              // 938

// ---------------- scratch (device globals; no allocations allowed) ----------
struct __align__(32) VAcc { float4 t; float4 c; };     // c.x = cnt, rest pad
__device__ VAcc     g_vacc[TOTAL_V];                   // 7.68 MB
__device__ float    g_partial[NB * MEAN_SUB * 4];      // mean partials (overwritten)
__device__ double   g_acc[3];                          // L1 sumsq, L2 sum, L3 sum
__device__ unsigned g_done;

__device__ __forceinline__ void red_add_v4(float4* addr, float a, float b, float c, float d)
{
    asm volatile("red.global.add.v4.f32 [%0], {%1, %2, %3, %4};"
                 :: "l"(addr), "f"(a), "f"(b), "f"(c), "f"(d) : "memory");
}

// ---------------- K0: zero scratch + mean partials ---------------------------
__global__ void __launch_bounds__(256) k_init(const float4* __restrict__ pred)
{
    int bid = blockIdx.x, tid = threadIdx.x;
    if (bid < ZERO_BLKS) {
        int gid = bid * 256 + tid;
        if (gid < TOTAL_V * 2)
            reinterpret_cast<float4*>(g_vacc)[gid] = make_float4(0.f, 0.f, 0.f, 0.f);
        if (bid == 0) {
            if (tid < 3) g_acc[tid] = 0.0;
            if (tid == 4) g_done = 0u;
        }
        return;
    }
    // mean partial: block handles (b, sub) slice, no atomics (pure overwrite)
    int mb = bid - ZERO_BLKS;
    int b = mb / MEAN_SUB, sub = mb % MEAN_SUB;
    float sx = 0.f, sy = 0.f, sz = 0.f, sw = 0.f;
    for (int i = sub * 256 + tid; i < NV; i += MEAN_SUB * 256) {
        float4 v = pred[b * NV + i];
        sx += v.x; sy += v.y; sz += v.z; sw += v.w;
    }
    #pragma unroll
    for (int o = 16; o; o >>= 1) {
        sx += __shfl_down_sync(0xFFFFFFFFu, sx, o);
        sy += __shfl_down_sync(0xFFFFFFFFu, sy, o);
        sz += __shfl_down_sync(0xFFFFFFFFu, sz, o);
        sw += __shfl_down_sync(0xFFFFFFFFu, sw, o);
    }
    __shared__ float sh[8][4];
    if ((tid & 31) == 0) {
        int w = tid >> 5;
        sh[w][0] = sx; sh[w][1] = sy; sh[w][2] = sz; sh[w][3] = sw;
    }
    __syncthreads();
    if (tid == 0) {
        float ax = 0.f, ay = 0.f, az = 0.f, aw = 0.f;
        #pragma unroll
        for (int i = 0; i < 8; i++) { ax += sh[i][0]; ay += sh[i][1]; az += sh[i][2]; aw += sh[i][3]; }
        float* p = &g_partial[(b * MEAN_SUB + sub) * 4];
        p[0] = ax; p[1] = ay; p[2] = az; p[3] = aw;
    }
}

// ---------------- K1: fused per-tet kernel -----------------------------------
__global__ void __launch_bounds__(256) k_tet(
    const float4* __restrict__ pred, const int4* __restrict__ tetra,
    float* __restrict__ out)
{
    __shared__ float s_pts[256 * 18];   // 18 KB
    __shared__ float s_msk[256 * 6];    //  6 KB
    __shared__ float s_mean[8];
    __shared__ float s2[8], s3[8];

    int tid = threadIdx.x;
    int gid = blockIdx.x * 256 + tid;
    bool valid = gid < TOTAL_T;

    // reduce mean partials (8 threads, L2-broadcast reads)
    if (tid < 8) {
        int b = tid >> 2, c = tid & 3;
        float s = 0.f;
        #pragma unroll
        for (int k = 0; k < MEAN_SUB; k++) s += g_partial[(b * MEAN_SUB + k) * 4 + c];
        s_mean[tid] = s * (1.f / (float)NV);
    }

    float l2sum = 0.f, l3sum = 0.f;
    float4 v[4];
    int b = 0;

    if (valid) {
        b = (gid >= NT) ? 1 : 0;
        int4 f = __ldcs(&tetra[gid]);          // streaming read-once
        const float4* p = pred + (size_t)b * NV;
        v[0] = p[f.x]; v[1] = p[f.y]; v[2] = p[f.z]; v[3] = p[f.w];

        float sx = v[0].x + v[1].x + v[2].x + v[3].x;
        float sy = v[0].y + v[1].y + v[2].y + v[3].y;
        float sz = v[0].z + v[1].z + v[2].z + v[3].z;
        float sw = v[0].w + v[1].w + v[2].w + v[3].w;

        // ---- Laplacian scatter (mean cancels); term+cnt share one 32B block --
        int base = b * NV;
        int vi[4] = {f.x, f.y, f.z, f.w};
        #pragma unroll
        for (int k = 0; k < 4; k++) {
            VAcc* a = &g_vacc[base + vi[k]];
            red_add_v4(&a->t, sx - 4.f * v[k].x, sy - 4.f * v[k].y,
                              sz - 4.f * v[k].z, sw - 4.f * v[k].w);
            atomicAdd(&a->c.x, 1.f);
        }
    }

    __syncthreads();   // s_mean ready

    if (valid) {
        float mx = s_mean[b * 4 + 0];
        float my = s_mean[b * 4 + 1];
        float mz = s_mean[b * 4 + 2];
        float mw = s_mean[b * 4 + 3];

        const int EA[6] = {0, 0, 0, 1, 1, 2};
        const int EB[6] = {1, 2, 3, 2, 3, 3};
        #pragma unroll
        for (int e = 0; e < 6; e++) {
            float4 va = v[EA[e]];
            float4 vb = v[EB[e]];
            float wa = va.w - mw;
            float wb = vb.w - mw;
            float prod = wa * wb;           // ALPHA = 0
            l2sum += prod;

            float dx = va.x - vb.x;         // mean cancels in diffs
            float dy = va.y - vb.y;
            float dz = va.z - vb.z;
            float dw = va.w - vb.w;
            float nrm = sqrtf(dx * dx + dy * dy + dz * dz + dw * dw);
            float l3 = nrm - 0.4f;
            l3sum += l3 * l3;

            float safe_q = (fabsf(dw) > 1e-12f) ? dw : 1.0f;
            float t = -wa / safe_q;

            bool m = prod < 0.f;
            float px = 0.f, py = 0.f, pz = 0.f;
            if (m) {
                px = (va.x - mx) + t * dx;
                py = (va.y - my) + t * dy;
                pz = (va.z - mz) + t * dz;
            }
            s_pts[tid * 18 + e * 3 + 0] = px;
            s_pts[tid * 18 + e * 3 + 1] = py;
            s_pts[tid * 18 + e * 3 + 2] = pz;
            s_msk[tid * 6 + e] = m ? 1.f : 0.f;
        }
    }

    // ---- block reduce L2 / L3 ----
    #pragma unroll
    for (int o = 16; o; o >>= 1) {
        l2sum += __shfl_down_sync(0xFFFFFFFFu, l2sum, o);
        l3sum += __shfl_down_sync(0xFFFFFFFFu, l3sum, o);
    }
    if ((tid & 31) == 0) { s2[tid >> 5] = l2sum; s3[tid >> 5] = l3sum; }
    __syncthreads();

    // ---- coalesced vectorized streaming writeout ----
    int nvalid = TOTAL_T - blockIdx.x * 256;
    if (nvalid > 256) nvalid = 256;

    const float4* sp4 = reinterpret_cast<const float4*>(s_pts);
    const float4* sm4 = reinterpret_cast<const float4*>(s_msk);

    float4* op = reinterpret_cast<float4*>(out + 4 + (size_t)blockIdx.x * (256 * 18));
    int np4 = nvalid * 18 / 4;
    for (int i = tid; i < np4; i += 256) __stcs(&op[i], sp4[i]);

    float4* om = reinterpret_cast<float4*>(out + 4 + PTS_FLOATS + (size_t)blockIdx.x * (256 * 6));
    int nm4 = nvalid * 6 / 4;
    for (int i = tid; i < nm4; i += 256) __stcs(&om[i], sm4[i]);

    if (tid == 0) {
        float a2 = 0.f, a3 = 0.f;
        #pragma unroll
        for (int i = 0; i < 8; i++) { a2 += s2[i]; a3 += s3[i]; }
        atomicAdd(&g_acc[1], (double)a2);
        atomicAdd(&g_acc[2], (double)a3);
    }
}

// ---------------- K2: per-vertex L1 finalize + loss writeout -----------------
__global__ void __launch_bounds__(256) k_vert_final(float* __restrict__ out)
{
    int gid = blockIdx.x * 256 + threadIdx.x;
    float s = 0.f;
    if (gid < TOTAL_V) {
        VAcc a = g_vacc[gid];
        float inv = 1.f / fmaxf(3.f * a.c.x, 1.f);
        float ax = a.t.x * inv, ay = a.t.y * inv, az = a.t.z * inv, aw = a.t.w * inv;
        s = ax * ax + ay * ay + az * az + aw * aw;
    }
    #pragma unroll
    for (int o = 16; o; o >>= 1) s += __shfl_down_sync(0xFFFFFFFFu, s, o);
    __shared__ float sh[8];
    if ((threadIdx.x & 31) == 0) sh[threadIdx.x >> 5] = s;
    __syncthreads();
    if (threadIdx.x == 0) {
        float a = 0.f;
        #pragma unroll
        for (int i = 0; i < 8; i++) a += sh[i];
        atomicAdd(&g_acc[0], (double)a);
        __threadfence();
        unsigned old = atomicInc(&g_done, 0xFFFFFFFFu);
        if (old == VERT_BLKS - 1) {
            out[0] = (float)(g_acc[0] / (double)((size_t)NB * NV * 4));
            out[1] = (float)(g_acc[1] / (double)TOTAL_E);
            out[2] = (float)(g_acc[2] / (double)TOTAL_E);
            out[3] = 0.f;
        }
    }
}

// ---------------- launch ------------------------------------------------------
extern "C" void kernel_launch(void* const* d_in, const int* in_sizes, int n_in,
                              void* d_out, int out_size)
{
    const float4* pred  = (const float4*)d_in[0];   // (B, N, 4) fp32
    const int4*   tetra = (const int4*)d_in[1];     // (B, T, 4) int32
    float* out = (float*)d_out;

    k_init<<<INIT_BLKS, 256>>>(pred);
    k_tet<<<(TOTAL_T + 255) / 256, 256>>>(pred, tetra, out);
    k_vert_final<<<VERT_BLKS, 256>>>(out);
}

// round 8
// speedup vs baseline: 3.1275x; 1.0369x over previous
#include <cuda_runtime.h>
#include <math.h>

#define NB 2
#define NV 120000
#define NT 600000

#define TOTAL_E (NB * NT * 6)       // 7,200,000
#define TOTAL_T (NB * NT)           // 1,200,000
#define TOTAL_V (NB * NV)           //   240,000
#define PTS_FLOATS ((size_t)TOTAL_E * 3)  // 21,600,000

#define MEAN_SUB 60
#define ZERO_BLKS 1500
#define INIT_BLKS (ZERO_BLKS + NB * MEAN_SUB)          // 1620
#define TET_BLK 128
#define TET_BLKS (TOTAL_T / TET_BLK)                   // 9375 exact
#define VERT_BLKS ((TOTAL_V + 255) / 256)              // 938

// ---------------- scratch (device globals; no allocations allowed) ----------
__device__ float4   g_term[TOTAL_V];                   // 3.84 MB
__device__ float    g_cnt[TOTAL_V];                    // 0.96 MB
__device__ float    g_partial[NB * MEAN_SUB * 4];      // mean partials (overwritten)
__device__ double   g_acc[3];                          // L1 sumsq, L2 sum, L3 sum
__device__ unsigned g_done;

__device__ __forceinline__ void red_add_v4(float4* addr, float a, float b, float c, float d)
{
    asm volatile("red.global.add.v4.f32 [%0], {%1, %2, %3, %4};"
                 :: "l"(addr), "f"(a), "f"(b), "f"(c), "f"(d) : "memory");
}

// ---------------- K0: zero scratch + mean partials (one kernel) --------------
__global__ void __launch_bounds__(256) k_init(const float4* __restrict__ pred)
{
    int bid = blockIdx.x, tid = threadIdx.x;

    if (bid < ZERO_BLKS) {
        // zero g_term (240000 float4) + g_cnt (60000 float4) = 300000 float4
        float4 z = make_float4(0.f, 0.f, 0.f, 0.f);
        float4* c4 = reinterpret_cast<float4*>(g_cnt);
        for (int i = bid * 256 + tid; i < 300000; i += ZERO_BLKS * 256) {
            if (i < TOTAL_V) g_term[i] = z;
            else             c4[i - TOTAL_V] = z;
        }
        if (bid == 0) {
            if (tid < 3) g_acc[tid] = 0.0;
            if (tid == 4) g_done = 0u;
        }
        return;
    }

    // mean partials: block (b, sub), plain overwrite, no atomics
    int mb = bid - ZERO_BLKS;
    int b = mb / MEAN_SUB, sub = mb % MEAN_SUB;
    float sx = 0.f, sy = 0.f, sz = 0.f, sw = 0.f;
    for (int i = sub * 256 + tid; i < NV; i += MEAN_SUB * 256) {
        float4 v = pred[b * NV + i];
        sx += v.x; sy += v.y; sz += v.z; sw += v.w;
    }
    #pragma unroll
    for (int o = 16; o; o >>= 1) {
        sx += __shfl_down_sync(0xFFFFFFFFu, sx, o);
        sy += __shfl_down_sync(0xFFFFFFFFu, sy, o);
        sz += __shfl_down_sync(0xFFFFFFFFu, sz, o);
        sw += __shfl_down_sync(0xFFFFFFFFu, sw, o);
    }
    __shared__ float sh[8][4];
    if ((tid & 31) == 0) {
        int w = tid >> 5;
        sh[w][0] = sx; sh[w][1] = sy; sh[w][2] = sz; sh[w][3] = sw;
    }
    __syncthreads();
    if (tid == 0) {
        float ax = 0.f, ay = 0.f, az = 0.f, aw = 0.f;
        #pragma unroll
        for (int i = 0; i < 8; i++) { ax += sh[i][0]; ay += sh[i][1]; az += sh[i][2]; aw += sh[i][3]; }
        float* p = &g_partial[(b * MEAN_SUB + sub) * 4];
        p[0] = ax; p[1] = ay; p[2] = az; p[3] = aw;
    }
}

// ---------------- K1: fused per-tet kernel (128 thr/blk, exact tiling) -------
__global__ void __launch_bounds__(TET_BLK) k_tet(
    const float4* __restrict__ pred, const int4* __restrict__ tetra,
    float* __restrict__ out)
{
    __shared__ float s_pts[TET_BLK * 18];   // 9 KB
    __shared__ float s_msk[TET_BLK * 6];    // 3 KB
    __shared__ float s_mean[8];
    __shared__ float s2[4], s3[4];

    int tid = threadIdx.x;
    int gid = blockIdx.x * TET_BLK + tid;   // always < TOTAL_T (exact tiling)

    if (tid < 8) {
        int b = tid >> 2, c = tid & 3;
        float s = 0.f;
        #pragma unroll
        for (int k = 0; k < MEAN_SUB; k++) s += g_partial[(b * MEAN_SUB + k) * 4 + c];
        s_mean[tid] = s * (1.f / (float)NV);
    }

    int b = (gid >= NT) ? 1 : 0;
    int4 f = __ldcs(&tetra[gid]);           // streaming read-once
    const float4* p = pred + (size_t)b * NV;
    float4 v[4];
    v[0] = p[f.x]; v[1] = p[f.y]; v[2] = p[f.z]; v[3] = p[f.w];

    float sx = v[0].x + v[1].x + v[2].x + v[3].x;
    float sy = v[0].y + v[1].y + v[2].y + v[3].y;
    float sz = v[0].z + v[1].z + v[2].z + v[3].z;
    float sw = v[0].w + v[1].w + v[2].w + v[3].w;

    // ---- Laplacian scatter (mean cancels in vsum - 4v) ----
    {
        int base = b * NV;
        int vi[4] = {f.x, f.y, f.z, f.w};
        #pragma unroll
        for (int k = 0; k < 4; k++) {
            red_add_v4(&g_term[base + vi[k]],
                       sx - 4.f * v[k].x, sy - 4.f * v[k].y,
                       sz - 4.f * v[k].z, sw - 4.f * v[k].w);
            atomicAdd(&g_cnt[base + vi[k]], 1.f);
        }
    }

    __syncthreads();   // s_mean ready

    float l2sum = 0.f, l3sum = 0.f;
    {
        float mx = s_mean[b * 4 + 0];
        float my = s_mean[b * 4 + 1];
        float mz = s_mean[b * 4 + 2];
        float mw = s_mean[b * 4 + 3];

        const int EA[6] = {0, 0, 0, 1, 1, 2};
        const int EB[6] = {1, 2, 3, 2, 3, 3};
        #pragma unroll
        for (int e = 0; e < 6; e++) {
            float4 va = v[EA[e]];
            float4 vb = v[EB[e]];
            float wa = va.w - mw;
            float wb = vb.w - mw;
            float prod = wa * wb;           // ALPHA = 0
            l2sum += prod;

            float dx = va.x - vb.x;         // mean cancels in diffs
            float dy = va.y - vb.y;
            float dz = va.z - vb.z;
            float dw = va.w - vb.w;
            float nrm = sqrtf(dx * dx + dy * dy + dz * dz + dw * dw);
            float l3 = nrm - 0.4f;
            l3sum += l3 * l3;

            float safe_q = (fabsf(dw) > 1e-12f) ? dw : 1.0f;
            float t = -wa / safe_q;

            bool m = prod < 0.f;
            float px = 0.f, py = 0.f, pz = 0.f;
            if (m) {
                px = (va.x - mx) + t * dx;
                py = (va.y - my) + t * dy;
                pz = (va.z - mz) + t * dz;
            }
            s_pts[tid * 18 + e * 3 + 0] = px;
            s_pts[tid * 18 + e * 3 + 1] = py;
            s_pts[tid * 18 + e * 3 + 2] = pz;
            s_msk[tid * 6 + e] = m ? 1.f : 0.f;
        }
    }

    // ---- block reduce L2 / L3 ----
    #pragma unroll
    for (int o = 16; o; o >>= 1) {
        l2sum += __shfl_down_sync(0xFFFFFFFFu, l2sum, o);
        l3sum += __shfl_down_sync(0xFFFFFFFFu, l3sum, o);
    }
    if ((tid & 31) == 0) { s2[tid >> 5] = l2sum; s3[tid >> 5] = l3sum; }
    __syncthreads();

    // ---- coalesced vectorized streaming writeout (bases 16B aligned) ----
    const float4* sp4 = reinterpret_cast<const float4*>(s_pts);
    const float4* sm4 = reinterpret_cast<const float4*>(s_msk);

    float4* op = reinterpret_cast<float4*>(out + 4 + (size_t)blockIdx.x * (TET_BLK * 18));
    #pragma unroll
    for (int r = 0; r < (TET_BLK * 18 / 4) / TET_BLK; r++)
        __stcs(&op[r * TET_BLK + tid], sp4[r * TET_BLK + tid]);
    {
        int i = (TET_BLK * 18 / 4) / TET_BLK * TET_BLK + tid;   // tail (576 = 4*128 + 64)
        if (i < TET_BLK * 18 / 4) __stcs(&op[i], sp4[i]);
    }

    float4* om = reinterpret_cast<float4*>(out + 4 + PTS_FLOATS + (size_t)blockIdx.x * (TET_BLK * 6));
    {
        int i = tid;                                            // 192 = 128 + 64
        __stcs(&om[i], sm4[i]);
        i += TET_BLK;
        if (i < TET_BLK * 6 / 4) __stcs(&om[i], sm4[i]);
    }

    if (tid == 0) {
        float a2 = 0.f, a3 = 0.f;
        #pragma unroll
        for (int i = 0; i < 4; i++) { a2 += s2[i]; a3 += s3[i]; }
        atomicAdd(&g_acc[1], (double)a2);
        atomicAdd(&g_acc[2], (double)a3);
    }
}

// ---------------- K2: per-vertex L1 finalize + loss writeout (R4-proven) -----
__global__ void __launch_bounds__(256) k_vert_final(float* __restrict__ out)
{
    int gid = blockIdx.x * 256 + threadIdx.x;
    float s = 0.f;
    if (gid < TOTAL_V) {
        float4 t = g_term[gid];
        float c = g_cnt[gid];
        float inv = 1.f / fmaxf(3.f * c, 1.f);
        float ax = t.x * inv, ay = t.y * inv, az = t.z * inv, aw = t.w * inv;
        s = ax * ax + ay * ay + az * az + aw * aw;
    }
    #pragma unroll
    for (int o = 16; o; o >>= 1) s += __shfl_down_sync(0xFFFFFFFFu, s, o);
    __shared__ float sh[8];
    if ((threadIdx.x & 31) == 0) sh[threadIdx.x >> 5] = s;
    __syncthreads();
    if (threadIdx.x == 0) {
        float a = 0.f;
        #pragma unroll
        for (int i = 0; i < 8; i++) a += sh[i];
        atomicAdd(&g_acc[0], (double)a);
        __threadfence();
        unsigned old = atomicInc(&g_done, 0xFFFFFFFFu);
        if (old == VERT_BLKS - 1) {
            out[0] = (float)(g_acc[0] / (double)((size_t)NB * NV * 4));
            out[1] = (float)(g_acc[1] / (double)TOTAL_E);
            out[2] = (float)(g_acc[2] / (double)TOTAL_E);
            out[3] = 0.f;
        }
    }
}

// ---------------- launch ------------------------------------------------------
extern "C" void kernel_launch(void* const* d_in, const int* in_sizes, int n_in,
                              void* d_out, int out_size)
{
    const float4* pred  = (const float4*)d_in[0];   // (B, N, 4) fp32
    const int4*   tetra = (const int4*)d_in[1];     // (B, T, 4) int32
    float* out = (float*)d_out;

    k_init<<<INIT_BLKS, 256>>>(pred);
    k_tet<<<TET_BLKS, TET_BLK>>>(pred, tetra, out);
    k_vert_final<<<VERT_BLKS, 256>>>(out);
}